// round 9
// baseline (speedup 1.0000x reference)
#include <cuda_runtime.h>
#include <cuda_bf16.h>
#include <math.h>
#include <stdint.h>

#define NS 19200   // T*H*W
#define TT 12
#define HH 40
#define WW 40
#define CC 128

// Scratch (device globals)
__device__ float    g_inv[NS];          // per-position inv-norm * sqrt(C)
__device__ uint32_t g_q[NS * 64];       // q rows, bf16x2, pre-scaled by C^-0.5
__device__ uint32_t g_k[NS * 64];       // k rows, bf16x2
__device__ uint32_t g_v[NS * 64];       // v rows, bf16x2
__device__ uint32_t g_att[NS * 64];     // attention output rows, bf16x2

__device__ __forceinline__ void mma_bf16(float* c, const uint32_t* a, const uint32_t* b) {
    asm volatile(
        "mma.sync.aligned.m16n8k16.row.col.f32.bf16.bf16.f32 "
        "{%0,%1,%2,%3}, {%4,%5,%6,%7}, {%8,%9}, {%0,%1,%2,%3};\n"
        : "+f"(c[0]), "+f"(c[1]), "+f"(c[2]), "+f"(c[3])
        : "r"(a[0]), "r"(a[1]), "r"(a[2]), "r"(a[3]), "r"(b[0]), "r"(b[1]));
}

__device__ __forceinline__ uint32_t pack_bf16(float x, float y) {
    uint32_t r;
    asm("cvt.rn.bf16x2.f32 %0, %1, %2;" : "=r"(r) : "f"(y), "f"(x));  // lo=x, hi=y
    return r;
}

// ---------------------------------------------------------------------------
// Kernel 1: per-position inv norm. inv[s] = sqrt(C)/max(||x[:,s]||,eps)
// ---------------------------------------------------------------------------
__global__ void inv_kernel(const float* __restrict__ x) {
    int s4 = (blockIdx.x * blockDim.x + threadIdx.x) * 4;
    if (s4 >= NS) return;
    float4 ss = {0.f, 0.f, 0.f, 0.f};
#pragma unroll 8
    for (int c = 0; c < CC; c++) {
        float4 v = *(const float4*)(x + (size_t)c * NS + s4);
        ss.x = fmaf(v.x, v.x, ss.x);
        ss.y = fmaf(v.y, v.y, ss.y);
        ss.z = fmaf(v.z, v.z, ss.z);
        ss.w = fmaf(v.w, v.w, ss.w);
    }
    const float sC = 11.313708498984761f;  // sqrt(128)
    float4 inv;
    inv.x = sC / fmaxf(sqrtf(ss.x), 1e-12f);
    inv.y = sC / fmaxf(sqrtf(ss.y), 1e-12f);
    inv.z = sC / fmaxf(sqrtf(ss.z), 1e-12f);
    inv.w = sC / fmaxf(sqrtf(ss.w), 1e-12f);
    *(float4*)(g_inv + s4) = inv;
}

// ---------------------------------------------------------------------------
// GEMM common bits
// ---------------------------------------------------------------------------
#define LDU 68
#define A_U (64 * LDU)          // 64-row tile in u32
#define B128_U (128 * LDU)      // 128-row tile in u32

// mainloop: warp tile 32x32; works for 4-warp (wn 0..1) and 8-warp (wn 0..3)
__device__ __forceinline__ void gemm_core(const uint32_t* As, const uint32_t* Bs,
                                          int wm, int wn, int g, int tg,
                                          float acc[2][4][4]) {
#pragma unroll
    for (int ks = 0; ks < 8; ks++) {
        int kb = ks * 8;
        uint32_t af[2][4], bf[4][2];
#pragma unroll
        for (int mt = 0; mt < 2; mt++) {
            int m = wm * 32 + mt * 16 + g;
            af[mt][0] = As[m * LDU + kb + tg];
            af[mt][1] = As[(m + 8) * LDU + kb + tg];
            af[mt][2] = As[m * LDU + kb + tg + 4];
            af[mt][3] = As[(m + 8) * LDU + kb + tg + 4];
        }
#pragma unroll
        for (int nt = 0; nt < 4; nt++) {
            int n = wn * 32 + nt * 8 + g;
            bf[nt][0] = Bs[n * LDU + kb + tg];
            bf[nt][1] = Bs[n * LDU + kb + tg + 4];
        }
#pragma unroll
        for (int mt = 0; mt < 2; mt++)
#pragma unroll
            for (int nt = 0; nt < 4; nt++)
                mma_bf16(acc[mt][nt], af[mt], bf[nt]);
    }
}

// ---------------------------------------------------------------------------
// Kernel 2: qkv GEMM. One CTA per 64-row A tile (grid=300, 256 thr).
// A staged ONCE (fused norm); loop over 3 weight blocks (q/k/v), restaging
// B each iteration from L2-hot qkv_w. Outputs bf16 (q pre-scaled C^-0.5).
// ---------------------------------------------------------------------------
#define QKV_SMEM ((A_U + B128_U) * 4)   // 52224 B
static_assert(QKV_SMEM <= 227 * 1024, "qkv smem");

__global__ void __launch_bounds__(256, 2)
gemm_qkv(const float* __restrict__ x, const float* __restrict__ gamma,
         const float* __restrict__ Bw, const float* __restrict__ bias) {
    extern __shared__ uint32_t su[];
    uint32_t* As = su;
    uint32_t* Bs = su + A_U;

    int tid = threadIdx.x;
    int lane = tid & 31;
    int warp = tid >> 5;
    int wm = warp & 1, wn = warp >> 1;   // 2M x 4N warps
    int g = lane >> 2, tg = lane & 3;
    int by = blockIdx.x;

    // Stage A once (64x128 fp32 + fused norm): 2048 float4, 8/thread
#pragma unroll
    for (int i = 0; i < 8; i++) {
        int id = tid + i * 256;
        int r = id >> 5, c4 = (id & 31) << 2;
        int row = by * 64 + r;
        int ch = row / 150;
        int s = (row - ch * 150) * 128 + c4;
        float gm = __ldg(&gamma[ch]);
        float4 iv = *(const float4*)(g_inv + s);
        float4 v = *(const float4*)(x + (size_t)row * 128 + c4);
        v.x *= iv.x * gm; v.y *= iv.y * gm; v.z *= iv.z * gm; v.w *= iv.w * gm;
        As[r * LDU + (c4 >> 1)]     = pack_bf16(v.x, v.y);
        As[r * LDU + (c4 >> 1) + 1] = pack_bf16(v.z, v.w);
    }

    const float QS = 0.08838834764831845f;  // C^-0.5

#pragma unroll
    for (int bx = 0; bx < 3; bx++) {
        // Stage B(bx): 128x128 fp32 -> bf16, 4096 float4, 16/thread (L2-hot)
        const float* Bbase = Bw + (size_t)bx * 128 * CC;
#pragma unroll
        for (int i = 0; i < 16; i++) {
            int id = tid + i * 256;
            int r = id >> 5, c4 = (id & 31) << 2;
            float4 v = *(const float4*)(Bbase + (size_t)r * CC + c4);
            Bs[r * LDU + (c4 >> 1)]     = pack_bf16(v.x, v.y);
            Bs[r * LDU + (c4 >> 1) + 1] = pack_bf16(v.z, v.w);
        }
        __syncthreads();

        float acc[2][4][4];
#pragma unroll
        for (int i = 0; i < 2; i++)
#pragma unroll
            for (int j = 0; j < 4; j++)
#pragma unroll
                for (int e = 0; e < 4; e++) acc[i][j][e] = 0.f;

        gemm_core(As, Bs, wm, wn, g, tg, acc);

        uint32_t* dst = (bx == 0) ? g_q : (bx == 1) ? g_k : g_v;
        float sc = (bx == 0) ? QS : 1.0f;
#pragma unroll
        for (int nt = 0; nt < 4; nt++) {
            int nloc = wn * 32 + nt * 8 + 2 * tg;   // even, 0..126
            float2 bb = *(const float2*)(bias + bx * 128 + nloc);
#pragma unroll
            for (int mt = 0; mt < 2; mt++) {
                int row0 = by * 64 + wm * 32 + mt * 16 + g;
                dst[row0 * 64 + (nloc >> 1)] =
                    pack_bf16((acc[mt][nt][0] + bb.x) * sc, (acc[mt][nt][1] + bb.y) * sc);
                dst[(row0 + 8) * 64 + (nloc >> 1)] =
                    pack_bf16((acc[mt][nt][2] + bb.x) * sc, (acc[mt][nt][3] + bb.y) * sc);
            }
        }
        __syncthreads();   // all mma reads of Bs done before next restage
    }
}

// ---------------------------------------------------------------------------
// Kernel 4: proj GEMM, 64x64 tiles, 128 thr (round-8 best: 12 us).
// A = g_att bf16 native; +bias +resid -> fp32 out.
// ---------------------------------------------------------------------------
#define PROJ_SMEM (2 * A_U * 4)   // 34816 B
static_assert(PROJ_SMEM <= 227 * 1024, "proj smem");

__global__ void __launch_bounds__(128, 5)
gemm_proj(const float* __restrict__ Bw, const float* __restrict__ bias,
          const float* __restrict__ resid, float* __restrict__ outArg) {
    extern __shared__ uint32_t su[];
    uint32_t* As = su;
    uint32_t* Bs = su + A_U;

    int tid = threadIdx.x;
    int lane = tid & 31;
    int warp = tid >> 5;
    int wm = warp & 1, wn = warp >> 1;   // 2M x 2N warps
    int g = lane >> 2, tg = lane & 3;

    const uint32_t* Abase = g_att + (size_t)blockIdx.y * 64 * 64;
#pragma unroll
    for (int i = 0; i < 8; i++) {
        int id = tid + i * 128;
        int r = id >> 4, c = (id & 15) * 4;
        uint4 v = *(const uint4*)(Abase + r * 64 + c);
        *(uint4*)(As + r * LDU + c) = v;
    }
    const float* Bbase = Bw + (size_t)blockIdx.x * 64 * CC;
#pragma unroll
    for (int i = 0; i < 16; i++) {
        int id = tid + i * 128;
        int r = id >> 5, c4 = (id & 31) << 2;
        float4 v = *(const float4*)(Bbase + (size_t)r * CC + c4);
        Bs[r * LDU + (c4 >> 1)]     = pack_bf16(v.x, v.y);
        Bs[r * LDU + (c4 >> 1) + 1] = pack_bf16(v.z, v.w);
    }
    __syncthreads();

    float acc[2][4][4];
#pragma unroll
    for (int i = 0; i < 2; i++)
#pragma unroll
        for (int j = 0; j < 4; j++)
#pragma unroll
            for (int e = 0; e < 4; e++) acc[i][j][e] = 0.f;

    gemm_core(As, Bs, wm, wn, g, tg, acc);

#pragma unroll
    for (int nt = 0; nt < 4; nt++) {
        int n = blockIdx.x * 64 + wn * 32 + nt * 8 + 2 * tg;
        float2 bb = *(const float2*)(bias + n);
#pragma unroll
        for (int mt = 0; mt < 2; mt++) {
            int row0 = blockIdx.y * 64 + wm * 32 + mt * 16 + g;
            float2 r0 = *(const float2*)(resid + (size_t)row0 * 128 + n);
            float2 r1 = *(const float2*)(resid + (size_t)(row0 + 8) * 128 + n);
            float2 o0 = { acc[mt][nt][0] + bb.x + r0.x, acc[mt][nt][1] + bb.y + r0.y };
            float2 o1 = { acc[mt][nt][2] + bb.x + r1.x, acc[mt][nt][3] + bb.y + r1.y };
            *(float2*)(outArg + (size_t)row0 * 128 + n) = o0;
            *(float2*)(outArg + (size_t)(row0 + 8) * 128 + n) = o1;
        }
    }
}

// ---------------------------------------------------------------------------
// Kernel 3: neighborhood attention. 16 positions/CTA (2t x 2h x 4w), union
// 4x4x6 = 96 bf16 k/v rows staged once (~65 KB smem, 3 CTAs/SM).
// Warp j owns positions j and j+8.
// ---------------------------------------------------------------------------
#define KPAD 66   // u32 per bf16 row

__global__ void __launch_bounds__(256)
attn_kernel(const float* __restrict__ rpb) {
    extern __shared__ float sm[];
    float*    qsm   = sm;                               // 16*132 floats
    uint32_t* ksm_u = (uint32_t*)(qsm + 16 * 132);      // 96*KPAD
    uint32_t* vsm_u = ksm_u + 96 * KPAD;                // 96*KPAD
    float*    sc    = (float*)(vsm_u + 96 * KPAD);      // 16*32
    float*    aw    = sc + 512;                         // 16*32
    int*      sl    = (int*)(aw + 512);                 // 16*32

    int tid = threadIdx.x, lane = tid & 31, warp = tid >> 5;
    int w0 = blockIdx.x * 4, h0 = blockIdx.y * 2, t0 = blockIdx.z * 2;

    int tlo = min(max(t0 - 1, 0), TT - 3);
    int hlo = min(max(h0 - 1, 0), HH - 3);
    int wlo = min(max(w0 - 1, 0), WW - 3);

    // bias + slot for all (pos, neighbor) pairs (432 of 512)
#pragma unroll
    for (int i = 0; i < 2; i++) {
        int d = tid + i * 256;
        if (d < 432) {
            int j = d / 27, n = d % 27;
            int pt = t0 + (j >> 3), ph = h0 + ((j >> 2) & 1), pw = w0 + (j & 3);
            int dt = n / 9, dh = (n / 3) % 3, dw = n % 3;
            int stt = min(max(pt - 1, 0), TT - 3);
            int sh  = min(max(ph - 1, 0), HH - 3);
            int sw  = min(max(pw - 1, 0), WW - 3);
            int nt = stt + dt, nh = sh + dh, nw = sw + dw;
            sl[j * 32 + n] = ((nt - tlo) * 4 + (nh - hlo)) * 6 + (nw - wlo);
            int bt = nt - pt + 2, bh = nh - ph + 2, bw = nw - pw + 2;
            sc[j * 32 + n] = __ldg(&rpb[(bt * 5 + bh) * 5 + bw]);
        }
    }

    // q staging (bf16 -> fp32 smem; already scaled); warp j -> pos j, j+8
#pragma unroll
    for (int i = 0; i < 2; i++) {
        int j = warp + i * 8;
        int pt = t0 + (j >> 3), ph = h0 + ((j >> 2) & 1), pw = w0 + (j & 3);
        int p = (pt * HH + ph) * WW + pw;
        uint2 qq = *(const uint2*)(g_q + p * 64 + lane * 2);
        float2 f0 = __bfloat1622float2(*(const __nv_bfloat162*)&qq.x);
        float2 f1 = __bfloat1622float2(*(const __nv_bfloat162*)&qq.y);
        float4 q4 = {f0.x, f0.y, f1.x, f1.y};
        *(float4*)(qsm + j * 132 + lane * 4) = q4;
    }

    // stage union k/v rows: 96 rows over 8 warps
    for (int rowid = warp; rowid < 96; rowid += 8) {
        int dt = rowid / 24, rrem = rowid % 24;
        int dh = rrem / 6, dw = rrem % 6;
        int nt = min(tlo + dt, TT - 1);
        int nh = min(hlo + dh, HH - 1);
        int nw = min(wlo + dw, WW - 1);
        int np = (nt * HH + nh) * WW + nw;
        *(uint2*)(ksm_u + rowid * KPAD + lane * 2) = *(const uint2*)(g_k + np * 64 + lane * 2);
        *(uint2*)(vsm_u + rowid * KPAD + lane * 2) = *(const uint2*)(g_v + np * 64 + lane * 2);
    }
    __syncthreads();

    // scores: 27 dot-128 per position, 2 positions per warp
#pragma unroll
    for (int i = 0; i < 2; i++) {
        int j = warp + i * 8;
        float4 q4 = *(const float4*)(qsm + j * 132 + lane * 4);
#pragma unroll
        for (int n = 0; n < 27; n++) {
            int slot = sl[j * 32 + n];
            uint2 kk = *(const uint2*)(ksm_u + slot * KPAD + lane * 2);
            float2 f0 = __bfloat1622float2(*(const __nv_bfloat162*)&kk.x);
            float2 f1 = __bfloat1622float2(*(const __nv_bfloat162*)&kk.y);
            float d = q4.x * f0.x + q4.y * f0.y + q4.z * f1.x + q4.w * f1.y;
#pragma unroll
            for (int o = 16; o; o >>= 1) d += __shfl_xor_sync(0xffffffffu, d, o);
            if (lane == 0) sc[j * 32 + n] += d;
        }
    }
    __syncwarp();

    // softmax per position
#pragma unroll
    for (int i = 0; i < 2; i++) {
        int j = warp + i * 8;
        float s = (lane < 27) ? sc[j * 32 + lane] : -1e30f;
        float m = s;
#pragma unroll
        for (int o = 16; o; o >>= 1) m = fmaxf(m, __shfl_xor_sync(0xffffffffu, m, o));
        float e = (lane < 27) ? __expf(s - m) : 0.f;
        float den = e;
#pragma unroll
        for (int o = 16; o; o >>= 1) den += __shfl_xor_sync(0xffffffffu, den, o);
        aw[j * 32 + lane] = e / den;
    }
    __syncwarp();

    // out = sum_n a_n * v_n, write bf16
#pragma unroll
    for (int i = 0; i < 2; i++) {
        int j = warp + i * 8;
        int pt = t0 + (j >> 3), ph = h0 + ((j >> 2) & 1), pw = w0 + (j & 3);
        int p = (pt * HH + ph) * WW + pw;
        float4 acc = {0.f, 0.f, 0.f, 0.f};
#pragma unroll
        for (int n = 0; n < 27; n++) {
            float a = aw[j * 32 + n];
            int slot = sl[j * 32 + n];
            uint2 vv = *(const uint2*)(vsm_u + slot * KPAD + lane * 2);
            float2 f0 = __bfloat1622float2(*(const __nv_bfloat162*)&vv.x);
            float2 f1 = __bfloat1622float2(*(const __nv_bfloat162*)&vv.y);
            acc.x = fmaf(a, f0.x, acc.x);
            acc.y = fmaf(a, f0.y, acc.y);
            acc.z = fmaf(a, f1.x, acc.z);
            acc.w = fmaf(a, f1.y, acc.w);
        }
        uint2 o = { pack_bf16(acc.x, acc.y), pack_bf16(acc.z, acc.w) };
        *(uint2*)(g_att + p * 64 + lane * 2) = o;
    }
}

static const int ATTN_SMEM = 16 * 132 * 4 + 96 * KPAD * 4 * 2 + 512 * 4 * 3;  // 65280 B
static_assert(16 * 132 * 4 + 96 * KPAD * 4 * 2 + 512 * 4 * 3 <= 227 * 1024, "attn smem");

// ---------------------------------------------------------------------------
extern "C" void kernel_launch(void* const* d_in, const int* in_sizes, int n_in,
                              void* d_out, int out_size) {
    const float* x      = (const float*)d_in[0];
    const float* gamma  = (const float*)d_in[1];
    const float* qkv_w  = (const float*)d_in[2];
    const float* qkv_b  = (const float*)d_in[3];
    const float* rpb    = (const float*)d_in[4];
    const float* proj_w = (const float*)d_in[5];
    const float* proj_b = (const float*)d_in[6];
    float* out = (float*)d_out;

    cudaFuncSetAttribute(attn_kernel, cudaFuncAttributeMaxDynamicSharedMemorySize, ATTN_SMEM);
    cudaFuncSetAttribute(gemm_qkv,  cudaFuncAttributeMaxDynamicSharedMemorySize, QKV_SMEM);
    cudaFuncSetAttribute(gemm_proj, cudaFuncAttributeMaxDynamicSharedMemorySize, PROJ_SMEM);

    inv_kernel<<<(NS / 4 + 255) / 256, 256>>>(x);
    gemm_qkv<<<NS / 64, 256, QKV_SMEM>>>(x, gamma, qkv_w, qkv_b);
    attn_kernel<<<dim3(WW / 4, HH / 2, TT / 2), 256, ATTN_SMEM>>>(rpb);
    gemm_proj<<<dim3(2, NS / 64), 128, PROJ_SMEM>>>(proj_w, proj_b, x, out);
}

// round 10
// speedup vs baseline: 1.1025x; 1.1025x over previous
#include <cuda_runtime.h>
#include <cuda_bf16.h>
#include <math.h>
#include <stdint.h>

#define NS 19200   // T*H*W
#define TT 12
#define HH 40
#define WW 40
#define CC 128

// Scratch (device globals)
__device__ float    g_inv[NS];           // per-position inv-norm * sqrt(C)
__device__ uint32_t g_q[NS * 64];        // q rows, bf16x2, pre-scaled by C^-0.5
__device__ uint32_t g_k[NS * 64];        // k rows, bf16x2
__device__ uint32_t g_v[NS * 64];        // v rows, bf16x2
__device__ uint32_t g_att[NS * 64];      // attention output rows, bf16x2
__device__ uint32_t g_wqkv[384 * 64];    // qkv_w bf16x2
__device__ uint32_t g_wproj[128 * 64];   // proj_w bf16x2

__device__ __forceinline__ void mma_bf16(float* c, const uint32_t* a, const uint32_t* b) {
    asm volatile(
        "mma.sync.aligned.m16n8k16.row.col.f32.bf16.bf16.f32 "
        "{%0,%1,%2,%3}, {%4,%5,%6,%7}, {%8,%9}, {%0,%1,%2,%3};\n"
        : "+f"(c[0]), "+f"(c[1]), "+f"(c[2]), "+f"(c[3])
        : "r"(a[0]), "r"(a[1]), "r"(a[2]), "r"(a[3]), "r"(b[0]), "r"(b[1]));
}

__device__ __forceinline__ uint32_t pack_bf16(float x, float y) {
    uint32_t r;
    asm("cvt.rn.bf16x2.f32 %0, %1, %2;" : "=r"(r) : "f"(y), "f"(x));  // lo=x, hi=y
    return r;
}

// ---------------------------------------------------------------------------
// Kernel 0: weight prep, fp32 -> bf16x2 (runs once per call; tiny)
// ---------------------------------------------------------------------------
__global__ void prep_w(const float* __restrict__ qkv_w, const float* __restrict__ proj_w) {
    int i = blockIdx.x * blockDim.x + threadIdx.x;   // 0 .. 32767
    if (i < 384 * 64) {
        float2 v = *(const float2*)(qkv_w + i * 2);
        g_wqkv[i] = pack_bf16(v.x, v.y);
    } else {
        int j = i - 384 * 64;
        float2 v = *(const float2*)(proj_w + j * 2);
        g_wproj[j] = pack_bf16(v.x, v.y);
    }
}

// ---------------------------------------------------------------------------
// Kernel 1: per-position inv norm. inv[s] = sqrt(C)/max(||x[:,s]||,eps)
// ---------------------------------------------------------------------------
__global__ void inv_kernel(const float* __restrict__ x) {
    int s4 = (blockIdx.x * blockDim.x + threadIdx.x) * 4;
    if (s4 >= NS) return;
    float4 ss = {0.f, 0.f, 0.f, 0.f};
#pragma unroll 8
    for (int c = 0; c < CC; c++) {
        float4 v = *(const float4*)(x + (size_t)c * NS + s4);
        ss.x = fmaf(v.x, v.x, ss.x);
        ss.y = fmaf(v.y, v.y, ss.y);
        ss.z = fmaf(v.z, v.z, ss.z);
        ss.w = fmaf(v.w, v.w, ss.w);
    }
    const float sC = 11.313708498984761f;  // sqrt(128)
    float4 inv;
    inv.x = sC / fmaxf(sqrtf(ss.x), 1e-12f);
    inv.y = sC / fmaxf(sqrtf(ss.y), 1e-12f);
    inv.z = sC / fmaxf(sqrtf(ss.z), 1e-12f);
    inv.w = sC / fmaxf(sqrtf(ss.w), 1e-12f);
    *(float4*)(g_inv + s4) = inv;
}

// ---------------------------------------------------------------------------
// GEMM common bits
// ---------------------------------------------------------------------------
#define LDU 68
#define A_U (64 * LDU)
#define B128_U (128 * LDU)

__device__ __forceinline__ void gemm_core(const uint32_t* As, const uint32_t* Bs,
                                          int wm, int wn, int g, int tg,
                                          float acc[2][4][4]) {
#pragma unroll
    for (int ks = 0; ks < 8; ks++) {
        int kb = ks * 8;
        uint32_t af[2][4], bf[4][2];
#pragma unroll
        for (int mt = 0; mt < 2; mt++) {
            int m = wm * 32 + mt * 16 + g;
            af[mt][0] = As[m * LDU + kb + tg];
            af[mt][1] = As[(m + 8) * LDU + kb + tg];
            af[mt][2] = As[m * LDU + kb + tg + 4];
            af[mt][3] = As[(m + 8) * LDU + kb + tg + 4];
        }
#pragma unroll
        for (int nt = 0; nt < 4; nt++) {
            int n = wn * 32 + nt * 8 + g;
            bf[nt][0] = Bs[n * LDU + kb + tg];
            bf[nt][1] = Bs[n * LDU + kb + tg + 4];
        }
#pragma unroll
        for (int mt = 0; mt < 2; mt++)
#pragma unroll
            for (int nt = 0; nt < 4; nt++)
                mma_bf16(acc[mt][nt], af[mt], bf[nt]);
    }
}

// ---------------------------------------------------------------------------
// Kernel 2: qkv GEMM (round-7 shape). Tile 64(M)x128(N), 256 thr = 8 warps
// (2M x 4N), grid (3, 300). A staged with fused norm; B straight bf16 copy.
// bf16 split epilogue (q pre-scaled by C^-0.5).
// ---------------------------------------------------------------------------
#define QKV_SMEM ((A_U + B128_U) * 4)   // 52224 B
static_assert(QKV_SMEM <= 227 * 1024, "qkv smem");

__global__ void __launch_bounds__(256, 2)
gemm_qkv(const float* __restrict__ x, const float* __restrict__ gamma,
         const float* __restrict__ bias) {
    extern __shared__ uint32_t su[];
    uint32_t* As = su;
    uint32_t* Bs = su + A_U;

    int tid = threadIdx.x;
    int lane = tid & 31;
    int warp = tid >> 5;
    int wm = warp & 1, wn = warp >> 1;   // 2M x 4N
    int g = lane >> 2, tg = lane & 3;
    int bx = blockIdx.x, by = blockIdx.y;

    // Stage A (64x128 fp32 + fused norm): 2048 float4, 8/thread
#pragma unroll
    for (int i = 0; i < 8; i++) {
        int id = tid + i * 256;
        int r = id >> 5, c4 = (id & 31) << 2;
        int row = by * 64 + r;
        int ch = row / 150;
        int s = (row - ch * 150) * 128 + c4;
        float gm = __ldg(&gamma[ch]);
        float4 iv = *(const float4*)(g_inv + s);
        float4 v = *(const float4*)(x + (size_t)row * 128 + c4);
        v.x *= iv.x * gm; v.y *= iv.y * gm; v.z *= iv.z * gm; v.w *= iv.w * gm;
        As[r * LDU + (c4 >> 1)]     = pack_bf16(v.x, v.y);
        As[r * LDU + (c4 >> 1) + 1] = pack_bf16(v.z, v.w);
    }
    // Stage B: straight uint4 copy of bf16 weights (128 rows x 16 uint4), 8/thread
    const uint32_t* Bbase = g_wqkv + (size_t)bx * 128 * 64;
#pragma unroll
    for (int i = 0; i < 8; i++) {
        int id = tid + i * 256;
        int r = id >> 4, c = (id & 15) * 4;
        uint4 v = *(const uint4*)(Bbase + r * 64 + c);
        *(uint4*)(Bs + r * LDU + c) = v;
    }
    __syncthreads();

    float acc[2][4][4];
#pragma unroll
    for (int i = 0; i < 2; i++)
#pragma unroll
        for (int j = 0; j < 4; j++)
#pragma unroll
            for (int e = 0; e < 4; e++) acc[i][j][e] = 0.f;

    gemm_core(As, Bs, wm, wn, g, tg, acc);

    const float QS = 0.08838834764831845f;  // C^-0.5
    uint32_t* dst = (bx == 0) ? g_q : (bx == 1) ? g_k : g_v;
    float sc = (bx == 0) ? QS : 1.0f;
#pragma unroll
    for (int nt = 0; nt < 4; nt++) {
        int nloc = wn * 32 + nt * 8 + 2 * tg;   // even, 0..126
        float2 bb = *(const float2*)(bias + bx * 128 + nloc);
#pragma unroll
        for (int mt = 0; mt < 2; mt++) {
            int row0 = by * 64 + wm * 32 + mt * 16 + g;
            dst[row0 * 64 + (nloc >> 1)] =
                pack_bf16((acc[mt][nt][0] + bb.x) * sc, (acc[mt][nt][1] + bb.y) * sc);
            dst[(row0 + 8) * 64 + (nloc >> 1)] =
                pack_bf16((acc[mt][nt][2] + bb.x) * sc, (acc[mt][nt][3] + bb.y) * sc);
        }
    }
}

// ---------------------------------------------------------------------------
// Kernel 4: proj GEMM, 64x64 tiles, 128 thr (best measured: 12 us).
// A = g_att bf16 copy; B = g_wproj bf16 copy; +bias +resid -> fp32 out.
// ---------------------------------------------------------------------------
#define PROJ_SMEM (2 * A_U * 4)   // 34816 B
static_assert(PROJ_SMEM <= 227 * 1024, "proj smem");

__global__ void __launch_bounds__(128, 5)
gemm_proj(const float* __restrict__ bias,
          const float* __restrict__ resid, float* __restrict__ outArg) {
    extern __shared__ uint32_t su[];
    uint32_t* As = su;
    uint32_t* Bs = su + A_U;

    int tid = threadIdx.x;
    int lane = tid & 31;
    int warp = tid >> 5;
    int wm = warp & 1, wn = warp >> 1;   // 2M x 2N
    int g = lane >> 2, tg = lane & 3;

    const uint32_t* Abase = g_att + (size_t)blockIdx.y * 64 * 64;
#pragma unroll
    for (int i = 0; i < 8; i++) {
        int id = tid + i * 128;
        int r = id >> 4, c = (id & 15) * 4;
        uint4 v = *(const uint4*)(Abase + r * 64 + c);
        *(uint4*)(As + r * LDU + c) = v;
    }
    const uint32_t* Bbase = g_wproj + (size_t)blockIdx.x * 64 * 64;
#pragma unroll
    for (int i = 0; i < 8; i++) {
        int id = tid + i * 128;
        int r = id >> 4, c = (id & 15) * 4;
        uint4 v = *(const uint4*)(Bbase + r * 64 + c);
        *(uint4*)(Bs + r * LDU + c) = v;
    }
    __syncthreads();

    float acc[2][4][4];
#pragma unroll
    for (int i = 0; i < 2; i++)
#pragma unroll
        for (int j = 0; j < 4; j++)
#pragma unroll
            for (int e = 0; e < 4; e++) acc[i][j][e] = 0.f;

    gemm_core(As, Bs, wm, wn, g, tg, acc);

#pragma unroll
    for (int nt = 0; nt < 4; nt++) {
        int n = blockIdx.x * 64 + wn * 32 + nt * 8 + 2 * tg;
        float2 bb = *(const float2*)(bias + n);
#pragma unroll
        for (int mt = 0; mt < 2; mt++) {
            int row0 = blockIdx.y * 64 + wm * 32 + mt * 16 + g;
            float2 r0 = *(const float2*)(resid + (size_t)row0 * 128 + n);
            float2 r1 = *(const float2*)(resid + (size_t)(row0 + 8) * 128 + n);
            float2 o0 = { acc[mt][nt][0] + bb.x + r0.x, acc[mt][nt][1] + bb.y + r0.y };
            float2 o1 = { acc[mt][nt][2] + bb.x + r1.x, acc[mt][nt][3] + bb.y + r1.y };
            *(float2*)(outArg + (size_t)row0 * 128 + n) = o0;
            *(float2*)(outArg + (size_t)(row0 + 8) * 128 + n) = o1;
        }
    }
}

// ---------------------------------------------------------------------------
// Kernel 3: neighborhood attention (round-8 form). 8 positions/CTA
// (1t x 2h x 4w), union 3x4x6 = 72 bf16 k/v rows (45 KB smem, 5 CTAs/SM).
// ---------------------------------------------------------------------------
#define KPAD 66   // u32 per bf16 row

__global__ void __launch_bounds__(256)
attn_kernel(const float* __restrict__ rpb) {
    extern __shared__ float sm[];
    float*    qsm   = sm;                               // 8*132 floats
    uint32_t* ksm_u = (uint32_t*)(qsm + 8 * 132);       // 72*KPAD
    uint32_t* vsm_u = ksm_u + 72 * KPAD;                // 72*KPAD
    float*    sc    = (float*)(vsm_u + 72 * KPAD);      // 8*32
    float*    aw    = sc + 256;                         // 8*32
    int*      sl    = (int*)(aw + 256);                 // 8*32

    int tid = threadIdx.x, lane = tid & 31, warp = tid >> 5;
    int w0 = blockIdx.x * 4, h0 = blockIdx.y * 2, t = blockIdx.z;

    int st  = min(max(t  - 1, 0), TT - 3);
    int hlo = min(max(h0 - 1, 0), HH - 3);
    int wlo = min(max(w0 - 1, 0), WW - 3);

    int ph = h0 + (warp >> 2), pw = w0 + (warp & 3);
    int p  = (t * HH + ph) * WW + pw;

    if (lane < 27) {
        int dt = lane / 9, dh = (lane / 3) % 3, dw = lane % 3;
        int sh = min(max(ph - 1, 0), HH - 3);
        int sw = min(max(pw - 1, 0), WW - 3);
        int nt = st + dt, nh = sh + dh, nw = sw + dw;
        sl[warp * 32 + lane] = (dt * 4 + (nh - hlo)) * 6 + (nw - wlo);
        int bt = nt - t + 2, bh = nh - ph + 2, bw = nw - pw + 2;
        sc[warp * 32 + lane] = __ldg(&rpb[(bt * 5 + bh) * 5 + bw]);
    }

    // q: bf16 -> fp32 smem (already scaled)
    {
        uint2 qq = *(const uint2*)(g_q + p * 64 + lane * 2);
        float2 f0 = __bfloat1622float2(*(const __nv_bfloat162*)&qq.x);
        float2 f1 = __bfloat1622float2(*(const __nv_bfloat162*)&qq.y);
        float4 q4 = {f0.x, f0.y, f1.x, f1.y};
        *(float4*)(qsm + warp * 132 + lane * 4) = q4;
    }

    for (int rowid = warp; rowid < 72; rowid += 8) {
        int dt = rowid / 24, rrem = rowid % 24;
        int dh = rrem / 6, dw = rrem % 6;
        int nh = min(hlo + dh, HH - 1);
        int nw = min(wlo + dw, WW - 1);
        int np = ((st + dt) * HH + nh) * WW + nw;
        *(uint2*)(ksm_u + rowid * KPAD + lane * 2) = *(const uint2*)(g_k + np * 64 + lane * 2);
        *(uint2*)(vsm_u + rowid * KPAD + lane * 2) = *(const uint2*)(g_v + np * 64 + lane * 2);
    }
    __syncthreads();

    {
        float4 q4 = *(const float4*)(qsm + warp * 132 + lane * 4);
#pragma unroll
        for (int n = 0; n < 27; n++) {
            int slot = sl[warp * 32 + n];
            uint2 kk = *(const uint2*)(ksm_u + slot * KPAD + lane * 2);
            float2 f0 = __bfloat1622float2(*(const __nv_bfloat162*)&kk.x);
            float2 f1 = __bfloat1622float2(*(const __nv_bfloat162*)&kk.y);
            float d = q4.x * f0.x + q4.y * f0.y + q4.z * f1.x + q4.w * f1.y;
#pragma unroll
            for (int o = 16; o; o >>= 1) d += __shfl_xor_sync(0xffffffffu, d, o);
            if (lane == 0) sc[warp * 32 + n] += d;
        }
    }
    __syncwarp();

    {
        float s = (lane < 27) ? sc[warp * 32 + lane] : -1e30f;
        float m = s;
#pragma unroll
        for (int o = 16; o; o >>= 1) m = fmaxf(m, __shfl_xor_sync(0xffffffffu, m, o));
        float e = (lane < 27) ? __expf(s - m) : 0.f;
        float den = e;
#pragma unroll
        for (int o = 16; o; o >>= 1) den += __shfl_xor_sync(0xffffffffu, den, o);
        aw[warp * 32 + lane] = e / den;
    }
    __syncwarp();

    {
        float4 acc = {0.f, 0.f, 0.f, 0.f};
#pragma unroll
        for (int n = 0; n < 27; n++) {
            float a = aw[warp * 32 + n];
            int slot = sl[warp * 32 + n];
            uint2 vv = *(const uint2*)(vsm_u + slot * KPAD + lane * 2);
            float2 f0 = __bfloat1622float2(*(const __nv_bfloat162*)&vv.x);
            float2 f1 = __bfloat1622float2(*(const __nv_bfloat162*)&vv.y);
            acc.x = fmaf(a, f0.x, acc.x);
            acc.y = fmaf(a, f0.y, acc.y);
            acc.z = fmaf(a, f1.x, acc.z);
            acc.w = fmaf(a, f1.y, acc.w);
        }
        uint2 o = { pack_bf16(acc.x, acc.y), pack_bf16(acc.z, acc.w) };
        *(uint2*)(g_att + p * 64 + lane * 2) = o;
    }
}

static const int ATTN_SMEM = 8 * 132 * 4 + 72 * KPAD * 4 * 2 + 256 * 4 * 3;  // 45312 B
static_assert(8 * 132 * 4 + 72 * KPAD * 4 * 2 + 256 * 4 * 3 <= 227 * 1024, "attn smem");

// ---------------------------------------------------------------------------
extern "C" void kernel_launch(void* const* d_in, const int* in_sizes, int n_in,
                              void* d_out, int out_size) {
    const float* x      = (const float*)d_in[0];
    const float* gamma  = (const float*)d_in[1];
    const float* qkv_w  = (const float*)d_in[2];
    const float* qkv_b  = (const float*)d_in[3];
    const float* rpb    = (const float*)d_in[4];
    const float* proj_w = (const float*)d_in[5];
    const float* proj_b = (const float*)d_in[6];
    float* out = (float*)d_out;

    cudaFuncSetAttribute(attn_kernel, cudaFuncAttributeMaxDynamicSharedMemorySize, ATTN_SMEM);
    cudaFuncSetAttribute(gemm_qkv,  cudaFuncAttributeMaxDynamicSharedMemorySize, QKV_SMEM);
    cudaFuncSetAttribute(gemm_proj, cudaFuncAttributeMaxDynamicSharedMemorySize, PROJ_SMEM);

    prep_w<<<128, 256>>>(qkv_w, proj_w);                 // 32768 threads
    inv_kernel<<<(NS / 4 + 255) / 256, 256>>>(x);
    gemm_qkv<<<dim3(3, NS / 64), 256, QKV_SMEM>>>(x, gamma, qkv_b);
    attn_kernel<<<dim3(WW / 4, HH / 2, TT), 256, ATTN_SMEM>>>(rpb);
    gemm_proj<<<dim3(2, NS / 64), 128, PROJ_SMEM>>>(proj_b, x, out);
}

// round 11
// speedup vs baseline: 1.3035x; 1.1823x over previous
#include <cuda_runtime.h>
#include <cuda_bf16.h>
#include <math.h>
#include <stdint.h>

#define NS 19200   // T*H*W
#define TT 12
#define HH 40
#define WW 40
#define CC 128

// Scratch (device globals)
__device__ float    g_inv[NS];           // per-position inv-norm * sqrt(C)
__device__ uint32_t g_q[NS * 64];        // q rows, bf16x2, pre-scaled by C^-0.5
__device__ uint32_t g_k[NS * 64];        // k rows, bf16x2
__device__ uint32_t g_v[NS * 64];        // v rows, bf16x2
__device__ uint32_t g_att[NS * 64];      // attention output rows, bf16x2
__device__ uint32_t g_wqkv[384 * 64];    // qkv_w bf16x2
__device__ uint32_t g_wproj[128 * 64];   // proj_w bf16x2

__device__ __forceinline__ void mma_bf16(float* c, const uint32_t* a, const uint32_t* b) {
    asm volatile(
        "mma.sync.aligned.m16n8k16.row.col.f32.bf16.bf16.f32 "
        "{%0,%1,%2,%3}, {%4,%5,%6,%7}, {%8,%9}, {%0,%1,%2,%3};\n"
        : "+f"(c[0]), "+f"(c[1]), "+f"(c[2]), "+f"(c[3])
        : "r"(a[0]), "r"(a[1]), "r"(a[2]), "r"(a[3]), "r"(b[0]), "r"(b[1]));
}

__device__ __forceinline__ uint32_t pack_bf16(float x, float y) {
    uint32_t r;
    asm("cvt.rn.bf16x2.f32 %0, %1, %2;" : "=r"(r) : "f"(y), "f"(x));  // lo=x, hi=y
    return r;
}

// ---------------------------------------------------------------------------
// Kernel 0: weight prep, fp32 -> bf16x2
// ---------------------------------------------------------------------------
__global__ void prep_w(const float* __restrict__ qkv_w, const float* __restrict__ proj_w) {
    int i = blockIdx.x * blockDim.x + threadIdx.x;   // 0 .. 32767
    if (i < 384 * 64) {
        float2 v = *(const float2*)(qkv_w + i * 2);
        g_wqkv[i] = pack_bf16(v.x, v.y);
    } else {
        int j = i - 384 * 64;
        float2 v = *(const float2*)(proj_w + j * 2);
        g_wproj[j] = pack_bf16(v.x, v.y);
    }
}

// ---------------------------------------------------------------------------
// Kernel 1: per-position inv norm
// ---------------------------------------------------------------------------
__global__ void inv_kernel(const float* __restrict__ x) {
    int s4 = (blockIdx.x * blockDim.x + threadIdx.x) * 4;
    if (s4 >= NS) return;
    float4 ss = {0.f, 0.f, 0.f, 0.f};
#pragma unroll 8
    for (int c = 0; c < CC; c++) {
        float4 v = *(const float4*)(x + (size_t)c * NS + s4);
        ss.x = fmaf(v.x, v.x, ss.x);
        ss.y = fmaf(v.y, v.y, ss.y);
        ss.z = fmaf(v.z, v.z, ss.z);
        ss.w = fmaf(v.w, v.w, ss.w);
    }
    const float sC = 11.313708498984761f;  // sqrt(128)
    float4 inv;
    inv.x = sC / fmaxf(sqrtf(ss.x), 1e-12f);
    inv.y = sC / fmaxf(sqrtf(ss.y), 1e-12f);
    inv.z = sC / fmaxf(sqrtf(ss.z), 1e-12f);
    inv.w = sC / fmaxf(sqrtf(ss.w), 1e-12f);
    *(float4*)(g_inv + s4) = inv;
}

// ---------------------------------------------------------------------------
// GEMM common bits
// ---------------------------------------------------------------------------
#define LDU 68
#define A_U (64 * LDU)
#define B128_U (128 * LDU)

__device__ __forceinline__ void gemm_core(const uint32_t* As, const uint32_t* Bs,
                                          int wm, int wn, int g, int tg,
                                          float acc[2][4][4]) {
#pragma unroll
    for (int ks = 0; ks < 8; ks++) {
        int kb = ks * 8;
        uint32_t af[2][4], bf[4][2];
#pragma unroll
        for (int mt = 0; mt < 2; mt++) {
            int m = wm * 32 + mt * 16 + g;
            af[mt][0] = As[m * LDU + kb + tg];
            af[mt][1] = As[(m + 8) * LDU + kb + tg];
            af[mt][2] = As[m * LDU + kb + tg + 4];
            af[mt][3] = As[(m + 8) * LDU + kb + tg + 4];
        }
#pragma unroll
        for (int nt = 0; nt < 4; nt++) {
            int n = wn * 32 + nt * 8 + g;
            bf[nt][0] = Bs[n * LDU + kb + tg];
            bf[nt][1] = Bs[n * LDU + kb + tg + 4];
        }
#pragma unroll
        for (int mt = 0; mt < 2; mt++)
#pragma unroll
            for (int nt = 0; nt < 4; nt++)
                mma_bf16(acc[mt][nt], af[mt], bf[nt]);
    }
}

// ---------------------------------------------------------------------------
// Kernel 2: qkv GEMM (round-10 winner, unchanged)
// ---------------------------------------------------------------------------
#define QKV_SMEM ((A_U + B128_U) * 4)   // 52224 B
static_assert(QKV_SMEM <= 227 * 1024, "qkv smem");

__global__ void __launch_bounds__(256, 2)
gemm_qkv(const float* __restrict__ x, const float* __restrict__ gamma,
         const float* __restrict__ bias) {
    extern __shared__ uint32_t su[];
    uint32_t* As = su;
    uint32_t* Bs = su + A_U;

    int tid = threadIdx.x;
    int lane = tid & 31;
    int warp = tid >> 5;
    int wm = warp & 1, wn = warp >> 1;
    int g = lane >> 2, tg = lane & 3;
    int bx = blockIdx.x, by = blockIdx.y;

#pragma unroll
    for (int i = 0; i < 8; i++) {
        int id = tid + i * 256;
        int r = id >> 5, c4 = (id & 31) << 2;
        int row = by * 64 + r;
        int ch = row / 150;
        int s = (row - ch * 150) * 128 + c4;
        float gm = __ldg(&gamma[ch]);
        float4 iv = *(const float4*)(g_inv + s);
        float4 v = *(const float4*)(x + (size_t)row * 128 + c4);
        v.x *= iv.x * gm; v.y *= iv.y * gm; v.z *= iv.z * gm; v.w *= iv.w * gm;
        As[r * LDU + (c4 >> 1)]     = pack_bf16(v.x, v.y);
        As[r * LDU + (c4 >> 1) + 1] = pack_bf16(v.z, v.w);
    }
    const uint32_t* Bbase = g_wqkv + (size_t)bx * 128 * 64;
#pragma unroll
    for (int i = 0; i < 8; i++) {
        int id = tid + i * 256;
        int r = id >> 4, c = (id & 15) * 4;
        uint4 v = *(const uint4*)(Bbase + r * 64 + c);
        *(uint4*)(Bs + r * LDU + c) = v;
    }
    __syncthreads();

    float acc[2][4][4];
#pragma unroll
    for (int i = 0; i < 2; i++)
#pragma unroll
        for (int j = 0; j < 4; j++)
#pragma unroll
            for (int e = 0; e < 4; e++) acc[i][j][e] = 0.f;

    gemm_core(As, Bs, wm, wn, g, tg, acc);

    const float QS = 0.08838834764831845f;
    uint32_t* dst = (bx == 0) ? g_q : (bx == 1) ? g_k : g_v;
    float sc = (bx == 0) ? QS : 1.0f;
#pragma unroll
    for (int nt = 0; nt < 4; nt++) {
        int nloc = wn * 32 + nt * 8 + 2 * tg;
        float2 bb = *(const float2*)(bias + bx * 128 + nloc);
#pragma unroll
        for (int mt = 0; mt < 2; mt++) {
            int row0 = by * 64 + wm * 32 + mt * 16 + g;
            dst[row0 * 64 + (nloc >> 1)] =
                pack_bf16((acc[mt][nt][0] + bb.x) * sc, (acc[mt][nt][1] + bb.y) * sc);
            dst[(row0 + 8) * 64 + (nloc >> 1)] =
                pack_bf16((acc[mt][nt][2] + bb.x) * sc, (acc[mt][nt][3] + bb.y) * sc);
        }
    }
}

// ---------------------------------------------------------------------------
// Kernel 4: proj GEMM (round-10 winner, unchanged)
// ---------------------------------------------------------------------------
#define PROJ_SMEM (2 * A_U * 4)   // 34816 B
static_assert(PROJ_SMEM <= 227 * 1024, "proj smem");

__global__ void __launch_bounds__(128, 5)
gemm_proj(const float* __restrict__ bias,
          const float* __restrict__ resid, float* __restrict__ outArg) {
    extern __shared__ uint32_t su[];
    uint32_t* As = su;
    uint32_t* Bs = su + A_U;

    int tid = threadIdx.x;
    int lane = tid & 31;
    int warp = tid >> 5;
    int wm = warp & 1, wn = warp >> 1;
    int g = lane >> 2, tg = lane & 3;

    const uint32_t* Abase = g_att + (size_t)blockIdx.y * 64 * 64;
#pragma unroll
    for (int i = 0; i < 8; i++) {
        int id = tid + i * 128;
        int r = id >> 4, c = (id & 15) * 4;
        uint4 v = *(const uint4*)(Abase + r * 64 + c);
        *(uint4*)(As + r * LDU + c) = v;
    }
    const uint32_t* Bbase = g_wproj + (size_t)blockIdx.x * 64 * 64;
#pragma unroll
    for (int i = 0; i < 8; i++) {
        int id = tid + i * 128;
        int r = id >> 4, c = (id & 15) * 4;
        uint4 v = *(const uint4*)(Bbase + r * 64 + c);
        *(uint4*)(Bs + r * LDU + c) = v;
    }
    __syncthreads();

    float acc[2][4][4];
#pragma unroll
    for (int i = 0; i < 2; i++)
#pragma unroll
        for (int j = 0; j < 4; j++)
#pragma unroll
            for (int e = 0; e < 4; e++) acc[i][j][e] = 0.f;

    gemm_core(As, Bs, wm, wn, g, tg, acc);

#pragma unroll
    for (int nt = 0; nt < 4; nt++) {
        int n = blockIdx.x * 64 + wn * 32 + nt * 8 + 2 * tg;
        float2 bb = *(const float2*)(bias + n);
#pragma unroll
        for (int mt = 0; mt < 2; mt++) {
            int row0 = blockIdx.y * 64 + wm * 32 + mt * 16 + g;
            float2 r0 = *(const float2*)(resid + (size_t)row0 * 128 + n);
            float2 r1 = *(const float2*)(resid + (size_t)(row0 + 8) * 128 + n);
            float2 o0 = { acc[mt][nt][0] + bb.x + r0.x, acc[mt][nt][1] + bb.y + r0.y };
            float2 o1 = { acc[mt][nt][2] + bb.x + r1.x, acc[mt][nt][3] + bb.y + r1.y };
            *(float2*)(outArg + (size_t)row0 * 128 + n) = o0;
            *(float2*)(outArg + (size_t)(row0 + 8) * 128 + n) = o1;
        }
    }
}

// ---------------------------------------------------------------------------
// Kernel 3: neighborhood attention with MMA score phase.
// 8 positions/CTA (1t x 2h x 4w), union 3x4x6 = 72 bf16 k/v rows.
// Scores = Q(16pad x 128) x K_union(72 x 128)^T via 9 m16n8k16 tiles.
// ---------------------------------------------------------------------------
#define VPAD 66   // u32 stride for v rows (scalar AV phase)
#define SCW 88    // scall row stride (floats)

__global__ void __launch_bounds__(256)
attn_kernel(const float* __restrict__ rpb) {
    extern __shared__ uint32_t smu[];
    uint32_t* qsm   = smu;                      // [16][LDU] bf16x2 (8 real + 8 zero)
    uint32_t* ksm   = qsm + 16 * LDU;           // [72][LDU]
    uint32_t* vsm   = ksm + 72 * LDU;           // [72][VPAD]
    float*    scall = (float*)(vsm + 72 * VPAD);// [8][SCW] raw mma scores
    float*    sc    = scall + 8 * SCW;          // [8][32] bias
    float*    aw    = sc + 256;                 // [8][32] softmax weights
    int*      sl    = (int*)(aw + 256);         // [8][32] slots

    int tid = threadIdx.x, lane = tid & 31, warp = tid >> 5;
    int g = lane >> 2, tg = lane & 3;
    int w0 = blockIdx.x * 4, h0 = blockIdx.y * 2, t = blockIdx.z;

    int st  = min(max(t  - 1, 0), TT - 3);
    int hlo = min(max(h0 - 1, 0), HH - 3);
    int wlo = min(max(w0 - 1, 0), WW - 3);

    int ph = h0 + (warp >> 2), pw = w0 + (warp & 3);
    int p  = (t * HH + ph) * WW + pw;

    if (lane < 27) {
        int dt = lane / 9, dh = (lane / 3) % 3, dw = lane % 3;
        int sh = min(max(ph - 1, 0), HH - 3);
        int sw = min(max(pw - 1, 0), WW - 3);
        int nt = st + dt, nh = sh + dh, nw = sw + dw;
        sl[warp * 32 + lane] = (dt * 4 + (nh - hlo)) * 6 + (nw - wlo);
        int bt = nt - t + 2, bh = nh - ph + 2, bw = nw - pw + 2;
        sc[warp * 32 + lane] = __ldg(&rpb[(bt * 5 + bh) * 5 + bw]);
    }

    // q: raw bf16 copy, warp w -> row w; zero row w+8 (mma M-padding)
    {
        *(uint2*)(qsm + warp * LDU + lane * 2) = *(const uint2*)(g_q + p * 64 + lane * 2);
        uint2 z = {0u, 0u};
        *(uint2*)(qsm + (warp + 8) * LDU + lane * 2) = z;
    }

    // stage union k/v rows
    for (int rowid = warp; rowid < 72; rowid += 8) {
        int dt = rowid / 24, rrem = rowid % 24;
        int dh = rrem / 6, dw = rrem % 6;
        int nh = min(hlo + dh, HH - 1);
        int nw = min(wlo + dw, WW - 1);
        int np = ((st + dt) * HH + nh) * WW + nw;
        *(uint2*)(ksm + rowid * LDU + lane * 2) = *(const uint2*)(g_k + np * 64 + lane * 2);
        *(uint2*)(vsm + rowid * VPAD + lane * 2) = *(const uint2*)(g_v + np * 64 + lane * 2);
    }
    __syncthreads();

    // MMA score phase: warp w computes n-tile w (warp 0 also tile 8).
    // A-frags (q) are tile-invariant: load once.
    {
        uint32_t af[8][4];
#pragma unroll
        for (int ks = 0; ks < 8; ks++) {
            int kb = ks * 8;
            af[ks][0] = qsm[g * LDU + kb + tg];
            af[ks][1] = qsm[(g + 8) * LDU + kb + tg];
            af[ks][2] = qsm[g * LDU + kb + tg + 4];
            af[ks][3] = qsm[(g + 8) * LDU + kb + tg + 4];
        }
        int ntiles = (warp == 0) ? 2 : 1;
        for (int it = 0; it < ntiles; it++) {
            int tt = (it == 0) ? warp : 8;
            float a4[4] = {0.f, 0.f, 0.f, 0.f};
            int n = tt * 8 + g;
#pragma unroll
            for (int ks = 0; ks < 8; ks++) {
                int kb = ks * 8;
                uint32_t bf[2];
                bf[0] = ksm[n * LDU + kb + tg];
                bf[1] = ksm[n * LDU + kb + tg + 4];
                mma_bf16(a4, af[ks], bf);
            }
            // rows g (<8) valid: c0,c1 -> cols 2tg, 2tg+1 of this n-tile
            *(float2*)(scall + g * SCW + tt * 8 + 2 * tg) = make_float2(a4[0], a4[1]);
        }
    }
    __syncthreads();

    // softmax per position (warp j): gather 27 scores + bias
    {
        float s = -1e30f;
        if (lane < 27)
            s = sc[warp * 32 + lane] + scall[warp * SCW + sl[warp * 32 + lane]];
        float m = s;
#pragma unroll
        for (int o = 16; o; o >>= 1) m = fmaxf(m, __shfl_xor_sync(0xffffffffu, m, o));
        float e = (lane < 27) ? __expf(s - m) : 0.f;
        float den = e;
#pragma unroll
        for (int o = 16; o; o >>= 1) den += __shfl_xor_sync(0xffffffffu, den, o);
        aw[warp * 32 + lane] = e / den;
    }
    __syncwarp();

    // AV phase: out = sum_n a_n * v_n (scalar fma, bf16 v)
    {
        float4 acc = {0.f, 0.f, 0.f, 0.f};
#pragma unroll
        for (int n = 0; n < 27; n++) {
            float a = aw[warp * 32 + n];
            int slot = sl[warp * 32 + n];
            uint2 vv = *(const uint2*)(vsm + slot * VPAD + lane * 2);
            float2 f0 = __bfloat1622float2(*(const __nv_bfloat162*)&vv.x);
            float2 f1 = __bfloat1622float2(*(const __nv_bfloat162*)&vv.y);
            acc.x = fmaf(a, f0.x, acc.x);
            acc.y = fmaf(a, f0.y, acc.y);
            acc.z = fmaf(a, f1.x, acc.z);
            acc.w = fmaf(a, f1.y, acc.w);
        }
        uint2 o = { pack_bf16(acc.x, acc.y), pack_bf16(acc.z, acc.w) };
        *(uint2*)(g_att + p * 64 + lane * 2) = o;
    }
}

static const int ATTN_SMEM =
    (16 * LDU + 72 * LDU + 72 * VPAD) * 4 + (8 * SCW + 256 + 256 + 256) * 4;  // 48832 B
static_assert((16 * LDU + 72 * LDU + 72 * VPAD) * 4 + (8 * SCW + 768) * 4 <= 227 * 1024,
              "attn smem");

// ---------------------------------------------------------------------------
extern "C" void kernel_launch(void* const* d_in, const int* in_sizes, int n_in,
                              void* d_out, int out_size) {
    const float* x      = (const float*)d_in[0];
    const float* gamma  = (const float*)d_in[1];
    const float* qkv_w  = (const float*)d_in[2];
    const float* qkv_b  = (const float*)d_in[3];
    const float* rpb    = (const float*)d_in[4];
    const float* proj_w = (const float*)d_in[5];
    const float* proj_b = (const float*)d_in[6];
    float* out = (float*)d_out;

    cudaFuncSetAttribute(attn_kernel, cudaFuncAttributeMaxDynamicSharedMemorySize, ATTN_SMEM);
    cudaFuncSetAttribute(gemm_qkv,  cudaFuncAttributeMaxDynamicSharedMemorySize, QKV_SMEM);
    cudaFuncSetAttribute(gemm_proj, cudaFuncAttributeMaxDynamicSharedMemorySize, PROJ_SMEM);

    prep_w<<<128, 256>>>(qkv_w, proj_w);
    inv_kernel<<<(NS / 4 + 255) / 256, 256>>>(x);
    gemm_qkv<<<dim3(3, NS / 64), 256, QKV_SMEM>>>(x, gamma, qkv_b);
    attn_kernel<<<dim3(WW / 4, HH / 2, TT), 256, ATTN_SMEM>>>(rpb);
    gemm_proj<<<dim3(2, NS / 64), 128, PROJ_SMEM>>>(proj_b, x, out);
}

// round 12
// speedup vs baseline: 1.3869x; 1.0640x over previous
#include <cuda_runtime.h>
#include <cuda_bf16.h>
#include <math.h>
#include <stdint.h>

#define NS 19200   // T*H*W
#define TT 12
#define HH 40
#define WW 40
#define CC 128

// Scratch (device globals)
__device__ float    g_inv[NS];           // per-position inv-norm * sqrt(C)
__device__ uint32_t g_q[NS * 64];        // q rows, bf16x2, pre-scaled by C^-0.5
__device__ uint32_t g_k[NS * 64];        // k rows, bf16x2
__device__ uint32_t g_v[NS * 64];        // v rows, bf16x2
__device__ uint32_t g_att[NS * 64];      // attention output rows, bf16x2
__device__ uint32_t g_wqkv[384 * 64];    // qkv_w bf16x2
__device__ uint32_t g_wproj[128 * 64];   // proj_w bf16x2

__device__ __forceinline__ void mma_bf16(float* c, const uint32_t* a, const uint32_t* b) {
    asm volatile(
        "mma.sync.aligned.m16n8k16.row.col.f32.bf16.bf16.f32 "
        "{%0,%1,%2,%3}, {%4,%5,%6,%7}, {%8,%9}, {%0,%1,%2,%3};\n"
        : "+f"(c[0]), "+f"(c[1]), "+f"(c[2]), "+f"(c[3])
        : "r"(a[0]), "r"(a[1]), "r"(a[2]), "r"(a[3]), "r"(b[0]), "r"(b[1]));
}

__device__ __forceinline__ uint32_t pack_bf16(float x, float y) {
    uint32_t r;
    asm("cvt.rn.bf16x2.f32 %0, %1, %2;" : "=r"(r) : "f"(y), "f"(x));  // lo=x, hi=y
    return r;
}

// ---------------------------------------------------------------------------
// Kernel 0: weight prep, fp32 -> bf16x2
// ---------------------------------------------------------------------------
__global__ void prep_w(const float* __restrict__ qkv_w, const float* __restrict__ proj_w) {
    int i = blockIdx.x * blockDim.x + threadIdx.x;   // 0 .. 32767
    if (i < 384 * 64) {
        float2 v = *(const float2*)(qkv_w + i * 2);
        g_wqkv[i] = pack_bf16(v.x, v.y);
    } else {
        int j = i - 384 * 64;
        float2 v = *(const float2*)(proj_w + j * 2);
        g_wproj[j] = pack_bf16(v.x, v.y);
    }
}

// ---------------------------------------------------------------------------
// Kernel 1: per-position inv norm
// ---------------------------------------------------------------------------
__global__ void inv_kernel(const float* __restrict__ x) {
    int s4 = (blockIdx.x * blockDim.x + threadIdx.x) * 4;
    if (s4 >= NS) return;
    float4 ss = {0.f, 0.f, 0.f, 0.f};
#pragma unroll 8
    for (int c = 0; c < CC; c++) {
        float4 v = *(const float4*)(x + (size_t)c * NS + s4);
        ss.x = fmaf(v.x, v.x, ss.x);
        ss.y = fmaf(v.y, v.y, ss.y);
        ss.z = fmaf(v.z, v.z, ss.z);
        ss.w = fmaf(v.w, v.w, ss.w);
    }
    const float sC = 11.313708498984761f;  // sqrt(128)
    float4 inv;
    inv.x = sC / fmaxf(sqrtf(ss.x), 1e-12f);
    inv.y = sC / fmaxf(sqrtf(ss.y), 1e-12f);
    inv.z = sC / fmaxf(sqrtf(ss.z), 1e-12f);
    inv.w = sC / fmaxf(sqrtf(ss.w), 1e-12f);
    *(float4*)(g_inv + s4) = inv;
}

// ---------------------------------------------------------------------------
// GEMM common bits
// ---------------------------------------------------------------------------
#define LDU 68
#define A_U (64 * LDU)
#define B128_U (128 * LDU)

__device__ __forceinline__ void gemm_core(const uint32_t* As, const uint32_t* Bs,
                                          int wm, int wn, int g, int tg,
                                          float acc[2][4][4]) {
#pragma unroll
    for (int ks = 0; ks < 8; ks++) {
        int kb = ks * 8;
        uint32_t af[2][4], bf[4][2];
#pragma unroll
        for (int mt = 0; mt < 2; mt++) {
            int m = wm * 32 + mt * 16 + g;
            af[mt][0] = As[m * LDU + kb + tg];
            af[mt][1] = As[(m + 8) * LDU + kb + tg];
            af[mt][2] = As[m * LDU + kb + tg + 4];
            af[mt][3] = As[(m + 8) * LDU + kb + tg + 4];
        }
#pragma unroll
        for (int nt = 0; nt < 4; nt++) {
            int n = wn * 32 + nt * 8 + g;
            bf[nt][0] = Bs[n * LDU + kb + tg];
            bf[nt][1] = Bs[n * LDU + kb + tg + 4];
        }
#pragma unroll
        for (int mt = 0; mt < 2; mt++)
#pragma unroll
            for (int nt = 0; nt < 4; nt++)
                mma_bf16(acc[mt][nt], af[mt], bf[nt]);
    }
}

// ---------------------------------------------------------------------------
// Kernel 2: qkv GEMM (round-10/11 winner, unchanged)
// ---------------------------------------------------------------------------
#define QKV_SMEM ((A_U + B128_U) * 4)   // 52224 B
static_assert(QKV_SMEM <= 227 * 1024, "qkv smem");

__global__ void __launch_bounds__(256, 2)
gemm_qkv(const float* __restrict__ x, const float* __restrict__ gamma,
         const float* __restrict__ bias) {
    extern __shared__ uint32_t su[];
    uint32_t* As = su;
    uint32_t* Bs = su + A_U;

    int tid = threadIdx.x;
    int lane = tid & 31;
    int warp = tid >> 5;
    int wm = warp & 1, wn = warp >> 1;
    int g = lane >> 2, tg = lane & 3;
    int bx = blockIdx.x, by = blockIdx.y;

#pragma unroll
    for (int i = 0; i < 8; i++) {
        int id = tid + i * 256;
        int r = id >> 5, c4 = (id & 31) << 2;
        int row = by * 64 + r;
        int ch = row / 150;
        int s = (row - ch * 150) * 128 + c4;
        float gm = __ldg(&gamma[ch]);
        float4 iv = *(const float4*)(g_inv + s);
        float4 v = *(const float4*)(x + (size_t)row * 128 + c4);
        v.x *= iv.x * gm; v.y *= iv.y * gm; v.z *= iv.z * gm; v.w *= iv.w * gm;
        As[r * LDU + (c4 >> 1)]     = pack_bf16(v.x, v.y);
        As[r * LDU + (c4 >> 1) + 1] = pack_bf16(v.z, v.w);
    }
    const uint32_t* Bbase = g_wqkv + (size_t)bx * 128 * 64;
#pragma unroll
    for (int i = 0; i < 8; i++) {
        int id = tid + i * 256;
        int r = id >> 4, c = (id & 15) * 4;
        uint4 v = *(const uint4*)(Bbase + r * 64 + c);
        *(uint4*)(Bs + r * LDU + c) = v;
    }
    __syncthreads();

    float acc[2][4][4];
#pragma unroll
    for (int i = 0; i < 2; i++)
#pragma unroll
        for (int j = 0; j < 4; j++)
#pragma unroll
            for (int e = 0; e < 4; e++) acc[i][j][e] = 0.f;

    gemm_core(As, Bs, wm, wn, g, tg, acc);

    const float QS = 0.08838834764831845f;
    uint32_t* dst = (bx == 0) ? g_q : (bx == 1) ? g_k : g_v;
    float sc = (bx == 0) ? QS : 1.0f;
#pragma unroll
    for (int nt = 0; nt < 4; nt++) {
        int nloc = wn * 32 + nt * 8 + 2 * tg;
        float2 bb = *(const float2*)(bias + bx * 128 + nloc);
#pragma unroll
        for (int mt = 0; mt < 2; mt++) {
            int row0 = by * 64 + wm * 32 + mt * 16 + g;
            dst[row0 * 64 + (nloc >> 1)] =
                pack_bf16((acc[mt][nt][0] + bb.x) * sc, (acc[mt][nt][1] + bb.y) * sc);
            dst[(row0 + 8) * 64 + (nloc >> 1)] =
                pack_bf16((acc[mt][nt][2] + bb.x) * sc, (acc[mt][nt][3] + bb.y) * sc);
        }
    }
}

// ---------------------------------------------------------------------------
// Kernel 4: proj GEMM (round-10/11 winner, unchanged)
// ---------------------------------------------------------------------------
#define PROJ_SMEM (2 * A_U * 4)   // 34816 B
static_assert(PROJ_SMEM <= 227 * 1024, "proj smem");

__global__ void __launch_bounds__(128, 5)
gemm_proj(const float* __restrict__ bias,
          const float* __restrict__ resid, float* __restrict__ outArg) {
    extern __shared__ uint32_t su[];
    uint32_t* As = su;
    uint32_t* Bs = su + A_U;

    int tid = threadIdx.x;
    int lane = tid & 31;
    int warp = tid >> 5;
    int wm = warp & 1, wn = warp >> 1;
    int g = lane >> 2, tg = lane & 3;

    const uint32_t* Abase = g_att + (size_t)blockIdx.y * 64 * 64;
#pragma unroll
    for (int i = 0; i < 8; i++) {
        int id = tid + i * 128;
        int r = id >> 4, c = (id & 15) * 4;
        uint4 v = *(const uint4*)(Abase + r * 64 + c);
        *(uint4*)(As + r * LDU + c) = v;
    }
    const uint32_t* Bbase = g_wproj + (size_t)blockIdx.x * 64 * 64;
#pragma unroll
    for (int i = 0; i < 8; i++) {
        int id = tid + i * 128;
        int r = id >> 4, c = (id & 15) * 4;
        uint4 v = *(const uint4*)(Bbase + r * 64 + c);
        *(uint4*)(Bs + r * LDU + c) = v;
    }
    __syncthreads();

    float acc[2][4][4];
#pragma unroll
    for (int i = 0; i < 2; i++)
#pragma unroll
        for (int j = 0; j < 4; j++)
#pragma unroll
            for (int e = 0; e < 4; e++) acc[i][j][e] = 0.f;

    gemm_core(As, Bs, wm, wn, g, tg, acc);

#pragma unroll
    for (int nt = 0; nt < 4; nt++) {
        int n = blockIdx.x * 64 + wn * 32 + nt * 8 + 2 * tg;
        float2 bb = *(const float2*)(bias + n);
#pragma unroll
        for (int mt = 0; mt < 2; mt++) {
            int row0 = blockIdx.y * 64 + wm * 32 + mt * 16 + g;
            float2 r0 = *(const float2*)(resid + (size_t)row0 * 128 + n);
            float2 r1 = *(const float2*)(resid + (size_t)(row0 + 8) * 128 + n);
            float2 o0 = { acc[mt][nt][0] + bb.x + r0.x, acc[mt][nt][1] + bb.y + r0.y };
            float2 o1 = { acc[mt][nt][2] + bb.x + r1.x, acc[mt][nt][3] + bb.y + r1.y };
            *(float2*)(outArg + (size_t)row0 * 128 + n) = o0;
            *(float2*)(outArg + (size_t)(row0 + 8) * 128 + n) = o1;
        }
    }
}

// ---------------------------------------------------------------------------
// Kernel 3: neighborhood attention, 16 positions/CTA (2t x 2h x 4w).
// Union 4x4x6 = 96 bf16 k/v rows; np table kills redundant address math.
// Scores: Q(16 x 128) x K_union(96 x 128)^T = 12 m16n8k16 n-tiles, M fully used.
// ---------------------------------------------------------------------------
#define VPAD 66    // u32 stride for v rows
#define SCW 104    // scall row stride (floats), 96 + pad

__global__ void __launch_bounds__(256)
attn_kernel(const float* __restrict__ rpb) {
    extern __shared__ uint32_t smu[];
    uint32_t* qsm   = smu;                        // [16][LDU]
    uint32_t* ksm   = qsm + 16 * LDU;             // [96][LDU]
    uint32_t* vsm   = ksm + 96 * LDU;             // [96][VPAD]
    float*    scall = (float*)(vsm + 96 * VPAD);  // [16][SCW]
    float*    sc    = scall + 16 * SCW;           // [16][32] bias
    float*    aw    = sc + 512;                   // [16][32] weights
    int*      sl    = (int*)(aw + 512);           // [16][32] slots
    int*      np    = sl + 512;                   // [96] neighbor flat positions

    int tid = threadIdx.x, lane = tid & 31, warp = tid >> 5;
    int g = lane >> 2, tg = lane & 3;
    int w0 = blockIdx.x * 4, h0 = blockIdx.y * 2, t0 = blockIdx.z * 2;

    int tlo = min(max(t0 - 1, 0), TT - 3);
    int hlo = min(max(h0 - 1, 0), HH - 3);
    int wlo = min(max(w0 - 1, 0), WW - 3);

    // np table: one thread per union row
    if (tid < 96) {
        int dt = tid / 24, rrem = tid % 24;
        int dh = rrem / 6, dw = rrem % 6;
        int nt = min(tlo + dt, TT - 1);
        int nh = min(hlo + dh, HH - 1);
        int nw = min(wlo + dw, WW - 1);
        np[tid] = (nt * HH + nh) * WW + nw;
    }

    // bias + slot for all (pos, neighbor) pairs: 16*27 = 432
#pragma unroll
    for (int i = 0; i < 2; i++) {
        int d = tid + i * 256;
        if (d < 432) {
            int j = d / 27, n = d % 27;
            int pt = t0 + (j >> 3), ph = h0 + ((j >> 2) & 1), pw = w0 + (j & 3);
            int dt = n / 9, dh = (n / 3) % 3, dw = n % 3;
            int stt = min(max(pt - 1, 0), TT - 3);
            int sh  = min(max(ph - 1, 0), HH - 3);
            int sw  = min(max(pw - 1, 0), WW - 3);
            int nt = stt + dt, nh = sh + dh, nw = sw + dw;
            sl[j * 32 + n] = ((nt - tlo) * 4 + (nh - hlo)) * 6 + (nw - wlo);
            int bt = nt - pt + 2, bh = nh - ph + 2, bw = nw - pw + 2;
            sc[j * 32 + n] = __ldg(&rpb[(bt * 5 + bh) * 5 + bw]);
        }
    }

    // q: raw bf16 copy; warp w -> rows w and w+8
#pragma unroll
    for (int i = 0; i < 2; i++) {
        int j = warp + i * 8;
        int pt = t0 + (j >> 3), ph = h0 + ((j >> 2) & 1), pw = w0 + (j & 3);
        int p = (pt * HH + ph) * WW + pw;
        *(uint2*)(qsm + j * LDU + lane * 2) = *(const uint2*)(g_q + p * 64 + lane * 2);
    }
    __syncthreads();   // np table ready

    // stage union k/v rows via table
    for (int rowid = warp; rowid < 96; rowid += 8) {
        int base = np[rowid] * 64 + lane * 2;
        *(uint2*)(ksm + rowid * LDU + lane * 2) = *(const uint2*)(g_k + base);
        *(uint2*)(vsm + rowid * VPAD + lane * 2) = *(const uint2*)(g_v + base);
    }
    __syncthreads();

    // MMA score phase: 12 n-tiles; warp w does tile w, warps 0-3 also tile 8+w
    {
        uint32_t af[8][4];
#pragma unroll
        for (int ks = 0; ks < 8; ks++) {
            int kb = ks * 8;
            af[ks][0] = qsm[g * LDU + kb + tg];
            af[ks][1] = qsm[(g + 8) * LDU + kb + tg];
            af[ks][2] = qsm[g * LDU + kb + tg + 4];
            af[ks][3] = qsm[(g + 8) * LDU + kb + tg + 4];
        }
#pragma unroll
        for (int it = 0; it < 2; it++) {
            if (it == 1 && warp >= 4) break;
            int tt = (it == 0) ? warp : warp + 8;
            float a4[4] = {0.f, 0.f, 0.f, 0.f};
            int n = tt * 8 + g;
#pragma unroll
            for (int ks = 0; ks < 8; ks++) {
                int kb = ks * 8;
                uint32_t bf[2];
                bf[0] = ksm[n * LDU + kb + tg];
                bf[1] = ksm[n * LDU + kb + tg + 4];
                mma_bf16(a4, af[ks], bf);
            }
            *(float2*)(scall + g * SCW + tt * 8 + 2 * tg) = make_float2(a4[0], a4[1]);
            *(float2*)(scall + (g + 8) * SCW + tt * 8 + 2 * tg) = make_float2(a4[2], a4[3]);
        }
    }
    __syncthreads();

    // softmax per position: warp handles rows warp, warp+8
#pragma unroll
    for (int i = 0; i < 2; i++) {
        int j = warp + i * 8;
        float s = -1e30f;
        if (lane < 27)
            s = sc[j * 32 + lane] + scall[j * SCW + sl[j * 32 + lane]];
        float m = s;
#pragma unroll
        for (int o = 16; o; o >>= 1) m = fmaxf(m, __shfl_xor_sync(0xffffffffu, m, o));
        float e = (lane < 27) ? __expf(s - m) : 0.f;
        float den = e;
#pragma unroll
        for (int o = 16; o; o >>= 1) den += __shfl_xor_sync(0xffffffffu, den, o);
        aw[j * 32 + lane] = e / den;
    }
    __syncwarp();

    // AV phase
#pragma unroll
    for (int i = 0; i < 2; i++) {
        int j = warp + i * 8;
        int pt = t0 + (j >> 3), ph = h0 + ((j >> 2) & 1), pw = w0 + (j & 3);
        int p = (pt * HH + ph) * WW + pw;
        float4 acc = {0.f, 0.f, 0.f, 0.f};
#pragma unroll
        for (int n = 0; n < 27; n++) {
            float a = aw[j * 32 + n];
            int slot = sl[j * 32 + n];
            uint2 vv = *(const uint2*)(vsm + slot * VPAD + lane * 2);
            float2 f0 = __bfloat1622float2(*(const __nv_bfloat162*)&vv.x);
            float2 f1 = __bfloat1622float2(*(const __nv_bfloat162*)&vv.y);
            acc.x = fmaf(a, f0.x, acc.x);
            acc.y = fmaf(a, f0.y, acc.y);
            acc.z = fmaf(a, f1.x, acc.z);
            acc.w = fmaf(a, f1.y, acc.w);
        }
        uint2 o = { pack_bf16(acc.x, acc.y), pack_bf16(acc.z, acc.w) };
        *(uint2*)(g_att + p * 64 + lane * 2) = o;
    }
}

static const int ATTN_SMEM =
    (16 * LDU + 96 * LDU + 96 * VPAD + 16 * SCW + 512 * 3 + 96) * 4;  // 68992 B
static_assert((16 * LDU + 96 * LDU + 96 * VPAD + 16 * SCW + 512 * 3 + 96) * 4
              <= 227 * 1024, "attn smem");

// ---------------------------------------------------------------------------
extern "C" void kernel_launch(void* const* d_in, const int* in_sizes, int n_in,
                              void* d_out, int out_size) {
    const float* x      = (const float*)d_in[0];
    const float* gamma  = (const float*)d_in[1];
    const float* qkv_w  = (const float*)d_in[2];
    const float* qkv_b  = (const float*)d_in[3];
    const float* rpb    = (const float*)d_in[4];
    const float* proj_w = (const float*)d_in[5];
    const float* proj_b = (const float*)d_in[6];
    float* out = (float*)d_out;

    cudaFuncSetAttribute(attn_kernel, cudaFuncAttributeMaxDynamicSharedMemorySize, ATTN_SMEM);
    cudaFuncSetAttribute(gemm_qkv,  cudaFuncAttributeMaxDynamicSharedMemorySize, QKV_SMEM);
    cudaFuncSetAttribute(gemm_proj, cudaFuncAttributeMaxDynamicSharedMemorySize, PROJ_SMEM);

    prep_w<<<128, 256>>>(qkv_w, proj_w);
    inv_kernel<<<(NS / 4 + 255) / 256, 256>>>(x);
    gemm_qkv<<<dim3(3, NS / 64), 256, QKV_SMEM>>>(x, gamma, qkv_b);
    attn_kernel<<<dim3(WW / 4, HH / 2, TT / 2), 256, ATTN_SMEM>>>(rpb);
    gemm_proj<<<dim3(2, NS / 64), 128, PROJ_SMEM>>>(proj_b, x, out);
}